// round 1
// baseline (speedup 1.0000x reference)
#include <cuda_runtime.h>

#define TILE 16
#define OCB 8

// Scratch (allocation-free): max intermediate is conv1_1 out = 2*64*256*256 = 8388608 floats
__device__ float g_bufA[8388608];
// max ping-pong second buffer: pac2_1 out = 2*128*128*128 = 4194304 floats
__device__ float g_bufB[4194304];

// Generic fused (PAC-)conv3x3 + bias + ReLU.
// out[b,o,oh,ow] = relu(bias[o] + sum_ij kern[b,ij,oh*S,ow*S] * sum_c w[o,c,ij]*in[b,c,oh*S+i-1,ow*S+j-1])
// kern==nullptr -> plain conv. Input zero-padded by 1.
template<int STRIDE>
__global__ void __launch_bounds__(256) conv_pac_kernel(
    const float* __restrict__ in, const float* __restrict__ wgt,
    const float* __restrict__ bias, const float* __restrict__ kern,
    float* __restrict__ out,
    int Ci, int Co, int Hin, int Win, int Hout, int Wout, int tilesX)
{
    constexpr int IT = (TILE - 1) * STRIDE + 3;   // 18 (s1) or 33 (s2)
    __shared__ float s_in[IT * IT];
    __shared__ __align__(16) float s_w[OCB * 9];

    const int tid = threadIdx.x;
    const int tx = tid % TILE, ty = tid / TILE;
    const int tX = blockIdx.x % tilesX, tY = blockIdx.x / tilesX;
    const int ocg = blockIdx.y;
    const int b = blockIdx.z;
    const int oh = tY * TILE + ty, ow = tX * TILE + tx;

    // Per-pixel PAC kernel values: constant across the channel loop.
    float kreg[9];
    if (kern) {
        const float* kp = kern + ((size_t)b * 9) * Hin * Win
                               + (size_t)(oh * STRIDE) * Win + (ow * STRIDE);
        #pragma unroll
        for (int t = 0; t < 9; t++) kreg[t] = kp[(size_t)t * Hin * Win];
    } else {
        #pragma unroll
        for (int t = 0; t < 9; t++) kreg[t] = 1.0f;
    }

    float acc[OCB];
    #pragma unroll
    for (int u = 0; u < OCB; u++) acc[u] = 0.0f;

    const int r0 = tY * TILE * STRIDE - 1;
    const int c0 = tX * TILE * STRIDE - 1;

    for (int c = 0; c < Ci; c++) {
        __syncthreads();
        const float* ip = in + ((size_t)b * Ci + c) * Hin * Win;
        for (int idx = tid; idx < IT * IT; idx += 256) {
            int rr = idx / IT, cc = idx % IT;
            int gr = r0 + rr, gc = c0 + cc;
            float v = 0.0f;
            if (gr >= 0 && gr < Hin && gc >= 0 && gc < Win)
                v = ip[(size_t)gr * Win + gc];
            s_in[idx] = v;
        }
        if (tid < OCB * 9) {
            int u = tid / 9, ij = tid % 9;
            s_w[tid] = wgt[(((size_t)(ocg * OCB + u)) * Ci + c) * 9 + ij];
        }
        __syncthreads();

        // Broadcast weights into registers via vectorized shared loads.
        float wr[OCB * 9];
        #pragma unroll
        for (int k = 0; k < (OCB * 9) / 4; k++) {
            float4 v4 = reinterpret_cast<const float4*>(s_w)[k];
            wr[4 * k + 0] = v4.x; wr[4 * k + 1] = v4.y;
            wr[4 * k + 2] = v4.z; wr[4 * k + 3] = v4.w;
        }

        #pragma unroll
        for (int i = 0; i < 3; i++)
        #pragma unroll
        for (int j = 0; j < 3; j++) {
            float v = s_in[(ty * STRIDE + i) * IT + (tx * STRIDE + j)] * kreg[i * 3 + j];
            #pragma unroll
            for (int u = 0; u < OCB; u++)
                acc[u] += wr[u * 9 + i * 3 + j] * v;
        }
    }

    #pragma unroll
    for (int u = 0; u < OCB; u++) {
        int o = ocg * OCB + u;
        float v = acc[u] + bias[o];
        v = v > 0.0f ? v : 0.0f;
        out[(((size_t)b * Co + o) * Hout + oh) * Wout + ow] = v;
    }
}

// Gaussian PAC kernel: k[b,ij,h,w] = exp(-0.5*coeff^2 * sum_c (f[c,nb]-f[c,ctr])^2),
// zero-padded neighbors.
__global__ void pac_gauss_kernel(const float* __restrict__ f, float* __restrict__ out,
                                 int C, int H, int W, float coeff2)
{
    const int b = blockIdx.z;
    const int idx = blockIdx.x * blockDim.x + threadIdx.x;
    if (idx >= H * W) return;
    const int h = idx / W, w = idx % W;

    float acc[9];
    #pragma unroll
    for (int t = 0; t < 9; t++) acc[t] = 0.0f;

    const float* fb = f + (size_t)b * C * H * W;
    for (int c = 0; c < C; c++) {
        const float* fc = fb + (size_t)c * H * W;
        float ctr = fc[idx];
        #pragma unroll
        for (int i = 0; i < 3; i++)
        #pragma unroll
        for (int j = 0; j < 3; j++) {
            int hh = h + i - 1, ww = w + j - 1;
            float nb = (hh >= 0 && hh < H && ww >= 0 && ww < W) ? fc[hh * W + ww] : 0.0f;
            float d = nb - ctr;
            acc[i * 3 + j] += d * d;
        }
    }

    float* ob = out + (size_t)b * 9 * H * W;
    #pragma unroll
    for (int t = 0; t < 9; t++)
        ob[(size_t)t * H * W + idx] = expf(-0.5f * coeff2 * acc[t]);
}

static void conv_layer(const float* in, const float* w, const float* b,
                       const float* kern, float* out,
                       int Ci, int Co, int Hin, int Win, int stride)
{
    int Hout = Hin / stride, Wout = Win / stride;
    int tilesX = Wout / TILE, tilesY = Hout / TILE;
    dim3 grid(tilesX * tilesY, Co / OCB, 2);
    if (stride == 1)
        conv_pac_kernel<1><<<grid, 256>>>(in, w, b, kern, out, Ci, Co, Hin, Win, Hout, Wout, tilesX);
    else
        conv_pac_kernel<2><<<grid, 256>>>(in, w, b, kern, out, Ci, Co, Hin, Win, Hout, Wout, tilesX);
}

static void pac_layer(const float* f, float* out, int C, int H, int W, float coeff2)
{
    int hw = H * W;
    dim3 grid((hw + 255) / 256, 1, 2);
    pac_gauss_kernel<<<grid, 256>>>(f, out, C, H, W, coeff2);
}

extern "C" void kernel_launch(void* const* d_in, const int* in_sizes, int n_in,
                              void* d_out, int out_size)
{
    const float* x = (const float*)d_in[0];
    const float* W[14];
    const float* B[14];
    for (int i = 0; i < 14; i++) {
        W[i] = (const float*)d_in[1 + 2 * i];
        B[i] = (const float*)d_in[2 + 2 * i];
    }

    float* bufA; float* bufB;
    cudaGetSymbolAddress((void**)&bufA, g_bufA);
    cudaGetSymbolAddress((void**)&bufB, g_bufB);

    float* out = (float*)d_out;
    float* h1 = out;                     // 2*64*256*256   = 8388608
    float* h2 = h1 + 8388608;            // 2*128*128*128  = 4194304
    float* h3 = h2 + 4194304;            // 2*256*64*64    = 2097152
    float* h4 = h3 + 2097152;            // 2*512*32*32    = 1048576
    float* h5 = h4 + 1048576;            // 2*1024*16*16   = 524288
    float* k2 = h5 + 524288;             // 2*9*128*128    = 294912
    float* k3 = k2 + 294912;             // 2*9*64*64      = 73728
    float* k4 = k3 + 73728;              // 2*9*32*32      = 18432
    float* k5 = k4 + 18432;              // 2*9*16*16      = 4608

    const float KC2 = 1e-4f * 1e-4f;

    // Stage 1
    conv_layer(x,    W[0], B[0], nullptr, bufA, 1,  64, 256, 256, 1);
    conv_layer(bufA, W[1], B[1], nullptr, h1,   64, 64, 256, 256, 1);
    conv_layer(h1,   W[2], B[2], nullptr, bufA, 64, 64, 256, 256, 2);  // -> 2,64,128,128

    // Stage 2 (PAC)
    pac_layer(bufA, k2, 64, 128, 128, KC2);
    conv_layer(bufA, W[3], B[3], k2, bufB, 64,  128, 128, 128, 1);
    conv_layer(bufB, W[4], B[4], k2, h2,   128, 128, 128, 128, 1);
    conv_layer(h2,   W[5], B[5], k2, bufA, 128, 128, 128, 128, 2);     // -> 2,128,64,64

    // Stage 3
    pac_layer(bufA, k3, 128, 64, 64, KC2);
    conv_layer(bufA, W[6], B[6], k3, bufB, 128, 256, 64, 64, 1);
    conv_layer(bufB, W[7], B[7], k3, h3,   256, 256, 64, 64, 1);
    conv_layer(h3,   W[8], B[8], k3, bufA, 256, 256, 64, 64, 2);       // -> 2,256,32,32

    // Stage 4 (guidance scaled by 2.0 -> coeff^2 = 4)
    pac_layer(bufA, k4, 256, 32, 32, 4.0f);
    conv_layer(bufA, W[9],  B[9],  k4, bufB, 256, 512, 32, 32, 1);
    conv_layer(bufB, W[10], B[10], k4, h4,   512, 512, 32, 32, 1);
    conv_layer(h4,   W[11], B[11], k4, bufA, 512, 512, 32, 32, 2);     // -> 2,512,16,16

    // Stage 5
    pac_layer(bufA, k5, 512, 16, 16, KC2);
    conv_layer(bufA, W[12], B[12], k5, bufB, 512,  1024, 16, 16, 1);
    conv_layer(bufB, W[13], B[13], k5, h5,   1024, 1024, 16, 16, 1);
}

// round 2
// speedup vs baseline: 1.4112x; 1.4112x over previous
#include <cuda_runtime.h>

#define TILE 16
#define OCB 8

__device__ float g_bufA[8388608];
__device__ float g_bufB[4194304];

// Fused (PAC-)conv3x3 + bias + ReLU, CB channels per barrier, double-buffered smem.
// out[b,o,oh,ow] = relu(bias[o] + sum_ij kern[b,ij,oh*S,ow*S] * sum_c w[o,c,ij]*in[b,c,...])
template<int STRIDE, int CB>
__global__ void __launch_bounds__(256) conv_pac_kernel(
    const float* __restrict__ in, const float* __restrict__ wgt,
    const float* __restrict__ bias, const float* __restrict__ kern,
    float* __restrict__ out,
    int Ci, int Co, int Hin, int Win, int Hout, int Wout, int tilesX)
{
    constexpr int IT  = (TILE - 1) * STRIDE + 3;   // 18 (s1) or 33 (s2)
    constexpr int ITS = IT * IT;
    __shared__ float s_in[2][CB * ITS];
    __shared__ __align__(16) float s_w[2][CB * OCB * 9];

    const int tid = threadIdx.x;
    const int tx = tid % TILE, ty = tid / TILE;
    const int tX = blockIdx.x % tilesX, tY = blockIdx.x / tilesX;
    const int ocg = blockIdx.y;
    const int b = blockIdx.z;
    const int oh = tY * TILE + ty, ow = tX * TILE + tx;

    float kreg[9];
    if (kern) {
        const float* kp = kern + ((size_t)b * 9) * Hin * Win
                               + (size_t)(oh * STRIDE) * Win + (ow * STRIDE);
        #pragma unroll
        for (int t = 0; t < 9; t++) kreg[t] = kp[(size_t)t * Hin * Win];
    } else {
        #pragma unroll
        for (int t = 0; t < 9; t++) kreg[t] = 1.0f;
    }

    float acc[OCB];
    #pragma unroll
    for (int u = 0; u < OCB; u++) acc[u] = 0.0f;

    const int r0 = tY * TILE * STRIDE - 1;
    const int c0 = tX * TILE * STRIDE - 1;
    const int NG = Ci / CB;

    // Stage CB channels of input + weights into buffer `buf`.
    auto stage = [&](int cg, int buf) {
        const int cbase = cg * CB;
        const float* ibase = in + ((size_t)b * Ci + cbase) * Hin * Win;
        for (int idx = tid; idx < CB * ITS; idx += 256) {
            int c = idx / ITS, p = idx % ITS;
            int rr = p / IT, cc = p % IT;
            int gr = r0 + rr, gc = c0 + cc;
            float v = 0.0f;
            if (gr >= 0 && gr < Hin && gc >= 0 && gc < Win)
                v = ibase[(size_t)c * Hin * Win + (size_t)gr * Win + gc];
            s_in[buf][idx] = v;
        }
        for (int idx = tid; idx < CB * OCB * 9; idx += 256) {
            int c = idx / (OCB * 9);
            int r = idx % (OCB * 9);
            int u = r / 9, ij = r % 9;
            s_w[buf][idx] = wgt[(((size_t)(ocg * OCB + u)) * Ci + (cbase + c)) * 9 + ij];
        }
    };

    stage(0, 0);

    for (int cg = 0; cg < NG; cg++) {
        __syncthreads();
        if (cg + 1 < NG) stage(cg + 1, (cg + 1) & 1);   // overlap next stage with compute
        const int buf = cg & 1;

        #pragma unroll
        for (int c = 0; c < CB; c++) {
            float wr[OCB * 9];
            const float4* wp = reinterpret_cast<const float4*>(&s_w[buf][c * OCB * 9]);
            #pragma unroll
            for (int k = 0; k < (OCB * 9) / 4; k++) {
                float4 v4 = wp[k];
                wr[4 * k + 0] = v4.x; wr[4 * k + 1] = v4.y;
                wr[4 * k + 2] = v4.z; wr[4 * k + 3] = v4.w;
            }
            const float* sp = &s_in[buf][c * ITS];
            #pragma unroll
            for (int i = 0; i < 3; i++)
            #pragma unroll
            for (int j = 0; j < 3; j++) {
                float v = sp[(ty * STRIDE + i) * IT + (tx * STRIDE + j)] * kreg[i * 3 + j];
                #pragma unroll
                for (int u = 0; u < OCB; u++)
                    acc[u] += wr[u * 9 + i * 3 + j] * v;
            }
        }
    }

    #pragma unroll
    for (int u = 0; u < OCB; u++) {
        int o = ocg * OCB + u;
        float v = acc[u] + bias[o];
        v = v > 0.0f ? v : 0.0f;
        out[(((size_t)b * Co + o) * Hout + oh) * Wout + ow] = v;
    }
}

__global__ void pac_gauss_kernel(const float* __restrict__ f, float* __restrict__ out,
                                 int C, int H, int W, float coeff2)
{
    const int b = blockIdx.z;
    const int idx = blockIdx.x * blockDim.x + threadIdx.x;
    if (idx >= H * W) return;
    const int h = idx / W, w = idx % W;

    float acc[9];
    #pragma unroll
    for (int t = 0; t < 9; t++) acc[t] = 0.0f;

    const float* fb = f + (size_t)b * C * H * W;
    for (int c = 0; c < C; c++) {
        const float* fc = fb + (size_t)c * H * W;
        float ctr = fc[idx];
        #pragma unroll
        for (int i = 0; i < 3; i++)
        #pragma unroll
        for (int j = 0; j < 3; j++) {
            int hh = h + i - 1, ww = w + j - 1;
            float nb = (hh >= 0 && hh < H && ww >= 0 && ww < W) ? fc[hh * W + ww] : 0.0f;
            float d = nb - ctr;
            acc[i * 3 + j] += d * d;
        }
    }

    float* ob = out + (size_t)b * 9 * H * W;
    #pragma unroll
    for (int t = 0; t < 9; t++)
        ob[(size_t)t * H * W + idx] = expf(-0.5f * coeff2 * acc[t]);
}

static void conv_layer(const float* in, const float* w, const float* b,
                       const float* kern, float* out,
                       int Ci, int Co, int Hin, int Win, int stride)
{
    int Hout = Hin / stride, Wout = Win / stride;
    int tilesX = Wout / TILE, tilesY = Hout / TILE;
    dim3 grid(tilesX * tilesY, Co / OCB, 2);
    if (stride == 1) {
        if (Ci % 4 == 0)
            conv_pac_kernel<1, 4><<<grid, 256>>>(in, w, b, kern, out, Ci, Co, Hin, Win, Hout, Wout, tilesX);
        else
            conv_pac_kernel<1, 1><<<grid, 256>>>(in, w, b, kern, out, Ci, Co, Hin, Win, Hout, Wout, tilesX);
    } else {
        if (Ci % 4 == 0)
            conv_pac_kernel<2, 4><<<grid, 256>>>(in, w, b, kern, out, Ci, Co, Hin, Win, Hout, Wout, tilesX);
        else
            conv_pac_kernel<2, 1><<<grid, 256>>>(in, w, b, kern, out, Ci, Co, Hin, Win, Hout, Wout, tilesX);
    }
}

static void pac_layer(const float* f, float* out, int C, int H, int W, float coeff2)
{
    int hw = H * W;
    dim3 grid((hw + 255) / 256, 1, 2);
    pac_gauss_kernel<<<grid, 256>>>(f, out, C, H, W, coeff2);
}

extern "C" void kernel_launch(void* const* d_in, const int* in_sizes, int n_in,
                              void* d_out, int out_size)
{
    const float* x = (const float*)d_in[0];
    const float* W[14];
    const float* B[14];
    for (int i = 0; i < 14; i++) {
        W[i] = (const float*)d_in[1 + 2 * i];
        B[i] = (const float*)d_in[2 + 2 * i];
    }

    float* bufA; float* bufB;
    cudaGetSymbolAddress((void**)&bufA, g_bufA);
    cudaGetSymbolAddress((void**)&bufB, g_bufB);

    float* out = (float*)d_out;
    float* h1 = out;                     // 2*64*256*256   = 8388608
    float* h2 = h1 + 8388608;            // 2*128*128*128  = 4194304
    float* h3 = h2 + 4194304;            // 2*256*64*64    = 2097152
    float* h4 = h3 + 2097152;            // 2*512*32*32    = 1048576
    float* h5 = h4 + 1048576;            // 2*1024*16*16   = 524288
    float* k2 = h5 + 524288;             // 2*9*128*128    = 294912
    float* k3 = k2 + 294912;             // 2*9*64*64      = 73728
    float* k4 = k3 + 73728;              // 2*9*32*32      = 18432
    float* k5 = k4 + 18432;              // 2*9*16*16      = 4608

    const float KC2 = 1e-4f * 1e-4f;

    // Stage 1
    conv_layer(x,    W[0], B[0], nullptr, bufA, 1,  64, 256, 256, 1);
    conv_layer(bufA, W[1], B[1], nullptr, h1,   64, 64, 256, 256, 1);
    conv_layer(h1,   W[2], B[2], nullptr, bufA, 64, 64, 256, 256, 2);  // -> 2,64,128,128

    // Stage 2 (PAC)
    pac_layer(bufA, k2, 64, 128, 128, KC2);
    conv_layer(bufA, W[3], B[3], k2, bufB, 64,  128, 128, 128, 1);
    conv_layer(bufB, W[4], B[4], k2, h2,   128, 128, 128, 128, 1);
    conv_layer(h2,   W[5], B[5], k2, bufA, 128, 128, 128, 128, 2);     // -> 2,128,64,64

    // Stage 3
    pac_layer(bufA, k3, 128, 64, 64, KC2);
    conv_layer(bufA, W[6], B[6], k3, bufB, 128, 256, 64, 64, 1);
    conv_layer(bufB, W[7], B[7], k3, h3,   256, 256, 64, 64, 1);
    conv_layer(h3,   W[8], B[8], k3, bufA, 256, 256, 64, 64, 2);       // -> 2,256,32,32

    // Stage 4 (guidance scaled by 2.0 -> coeff^2 = 4)
    pac_layer(bufA, k4, 256, 32, 32, 4.0f);
    conv_layer(bufA, W[9],  B[9],  k4, bufB, 256, 512, 32, 32, 1);
    conv_layer(bufB, W[10], B[10], k4, h4,   512, 512, 32, 32, 1);
    conv_layer(h4,   W[11], B[11], k4, bufA, 512, 512, 32, 32, 2);     // -> 2,512,16,16

    // Stage 5
    pac_layer(bufA, k5, 512, 16, 16, KC2);
    conv_layer(bufA, W[12], B[12], k5, bufB, 512,  1024, 16, 16, 1);
    conv_layer(bufB, W[13], B[13], k5, h5,   1024, 1024, 16, 16, 1);
}

// round 3
// speedup vs baseline: 2.0359x; 1.4426x over previous
#include <cuda_runtime.h>
#include <cstdint>

#define TILE 16

__device__ float g_bufA[8388608];
__device__ float g_bufB[4194304];

__device__ __forceinline__ void cp_async4(uint32_t saddr, const float* gptr) {
    asm volatile("cp.async.ca.shared.global [%0], [%1], 4;" :: "r"(saddr), "l"(gptr));
}
#define CP_COMMIT() asm volatile("cp.async.commit_group;" ::: "memory")
#define CP_WAIT0()  asm volatile("cp.async.wait_group 0;" ::: "memory")

// Fused (PAC-)conv3x3 + bias + ReLU.
// f32x2-packed over output-channel pairs (8 outputs = 4 packed accumulators).
// cp.async staged, double-buffered, CB channels per barrier.
template<int STRIDE, int CB>
__global__ void __launch_bounds__(256) conv_pac_kernel(
    const float* __restrict__ in, const float* __restrict__ wgt,
    const float* __restrict__ bias, const float* __restrict__ kern,
    float* __restrict__ out,
    int Ci, int Co, int Hin, int Win, int Hout, int Wout, int tilesX)
{
    constexpr int IT  = (TILE - 1) * STRIDE + 3;   // 18 (s1) or 33 (s2)
    constexpr int ITS = IT * IT;
    __shared__ float s_in[2][CB * ITS];
    __shared__ __align__(16) float s_w[2][CB * 72];   // [c][tap][u], u fastest

    const int tid = threadIdx.x;
    const int tx = tid % TILE, ty = tid / TILE;
    const int tX = blockIdx.x % tilesX, tY = blockIdx.x / tilesX;
    const int ocg = blockIdx.y;
    const int b = blockIdx.z;
    const int oh = tY * TILE + ty, ow = tX * TILE + tx;
    const size_t HW = (size_t)Hin * Win;

    // Per-pixel PAC values: constant across the channel loop.
    float kreg[9];
    if (kern) {
        const float* kp = kern + ((size_t)b * 9) * HW
                               + (size_t)(oh * STRIDE) * Win + (ow * STRIDE);
        #pragma unroll
        for (int t = 0; t < 9; t++) kreg[t] = kp[(size_t)t * HW];
    } else {
        #pragma unroll
        for (int t = 0; t < 9; t++) kreg[t] = 1.0f;
    }

    unsigned long long acc[4];
    #pragma unroll
    for (int p = 0; p < 4; p++) acc[p] = 0ull;

    const int r0 = tY * TILE * STRIDE - 1;
    const int c0 = tX * TILE * STRIDE - 1;
    const int NG = Ci / CB;

    // Zero both input buffers once (padded border slots are never cp.async'd;
    // their positions are identical every group, so they stay zero).
    for (int idx = tid; idx < 2 * CB * ITS; idx += 256)
        (&s_in[0][0])[idx] = 0.0f;
    __syncthreads();

    const uint32_t sin0 = (uint32_t)__cvta_generic_to_shared(&s_in[0][0]);
    const uint32_t sin1 = (uint32_t)__cvta_generic_to_shared(&s_in[1][0]);
    const uint32_t sw0  = (uint32_t)__cvta_generic_to_shared(&s_w[0][0]);
    const uint32_t sw1  = (uint32_t)__cvta_generic_to_shared(&s_w[1][0]);

    auto stage = [&](int cg, int buf) {
        const int cbase = cg * CB;
        const float* ibase = in + ((size_t)b * Ci + cbase) * HW;
        const uint32_t sb = buf ? sin1 : sin0;
        for (int idx = tid; idx < CB * ITS; idx += 256) {
            int c = idx / ITS, p = idx % ITS;
            int rr = p / IT, cc = p % IT;
            int gr = r0 + rr, gc = c0 + cc;
            if (gr >= 0 && gr < Hin && gc >= 0 && gc < Win)
                cp_async4(sb + idx * 4, ibase + (size_t)c * HW + gr * Win + gc);
        }
        const uint32_t wb = buf ? sw1 : sw0;
        for (int idx = tid; idx < CB * 72; idx += 256) {
            int c = idx / 72, r = idx % 72;
            int ij = r / 8, u = r % 8;
            cp_async4(wb + idx * 4,
                      &wgt[(((size_t)(ocg * 8 + u)) * Ci + (cbase + c)) * 9 + ij]);
        }
    };

    stage(0, 0);
    CP_COMMIT();

    const int base_off = (ty * STRIDE) * IT + tx * STRIDE;

    for (int cg = 0; cg < NG; cg++) {
        CP_WAIT0();
        __syncthreads();
        if (cg + 1 < NG) { stage(cg + 1, (cg + 1) & 1); CP_COMMIT(); }
        const int buf = cg & 1;

        #pragma unroll
        for (int c = 0; c < CB; c++) {
            const float* sp = &s_in[buf][c * ITS + base_off];
            const ulonglong2* wp = reinterpret_cast<const ulonglong2*>(&s_w[buf][c * 72]);
            #pragma unroll
            for (int t = 0; t < 9; t++) {
                float v = sp[(t / 3) * IT + (t % 3)] * kreg[t];
                uint32_t vb = __float_as_uint(v);
                unsigned long long vv;
                asm("mov.b64 %0, {%1, %1};" : "=l"(vv) : "r"(vb));
                ulonglong2 wa = wp[2 * t];
                ulonglong2 wbv = wp[2 * t + 1];
                asm("fma.rn.f32x2 %0, %1, %2, %0;" : "+l"(acc[0]) : "l"(wa.x),  "l"(vv));
                asm("fma.rn.f32x2 %0, %1, %2, %0;" : "+l"(acc[1]) : "l"(wa.y),  "l"(vv));
                asm("fma.rn.f32x2 %0, %1, %2, %0;" : "+l"(acc[2]) : "l"(wbv.x), "l"(vv));
                asm("fma.rn.f32x2 %0, %1, %2, %0;" : "+l"(acc[3]) : "l"(wbv.y), "l"(vv));
            }
        }
    }

    #pragma unroll
    for (int p = 0; p < 4; p++) {
        float lo, hi;
        asm("mov.b64 {%0, %1}, %2;" : "=f"(lo), "=f"(hi) : "l"(acc[p]));
        int o0 = ocg * 8 + 2 * p;
        float v0 = lo + bias[o0];
        float v1 = hi + bias[o0 + 1];
        v0 = v0 > 0.0f ? v0 : 0.0f;
        v1 = v1 > 0.0f ? v1 : 0.0f;
        out[(((size_t)b * Co + o0)     * Hout + oh) * Wout + ow] = v0;
        out[(((size_t)b * Co + o0 + 1) * Hout + oh) * Wout + ow] = v1;
    }
}

__global__ void pac_gauss_kernel(const float* __restrict__ f, float* __restrict__ out,
                                 int C, int H, int W, float coeff2)
{
    const int b = blockIdx.z;
    const int idx = blockIdx.x * blockDim.x + threadIdx.x;
    if (idx >= H * W) return;
    const int h = idx / W, w = idx % W;

    float acc[9];
    #pragma unroll
    for (int t = 0; t < 9; t++) acc[t] = 0.0f;

    const float* fb = f + (size_t)b * C * H * W;
    for (int c = 0; c < C; c++) {
        const float* fc = fb + (size_t)c * H * W;
        float ctr = fc[idx];
        #pragma unroll
        for (int i = 0; i < 3; i++)
        #pragma unroll
        for (int j = 0; j < 3; j++) {
            int hh = h + i - 1, ww = w + j - 1;
            float nb = (hh >= 0 && hh < H && ww >= 0 && ww < W) ? fc[hh * W + ww] : 0.0f;
            float d = nb - ctr;
            acc[i * 3 + j] += d * d;
        }
    }

    float* ob = out + (size_t)b * 9 * H * W;
    #pragma unroll
    for (int t = 0; t < 9; t++)
        ob[(size_t)t * H * W + idx] = expf(-0.5f * coeff2 * acc[t]);
}

static void conv_layer(const float* in, const float* w, const float* b,
                       const float* kern, float* out,
                       int Ci, int Co, int Hin, int Win, int stride)
{
    int Hout = Hin / stride, Wout = Win / stride;
    int tilesX = Wout / TILE, tilesY = Hout / TILE;
    dim3 grid(tilesX * tilesY, Co / 8, 2);
    if (stride == 1) {
        if (Ci % 8 == 0)
            conv_pac_kernel<1, 8><<<grid, 256>>>(in, w, b, kern, out, Ci, Co, Hin, Win, Hout, Wout, tilesX);
        else
            conv_pac_kernel<1, 1><<<grid, 256>>>(in, w, b, kern, out, Ci, Co, Hin, Win, Hout, Wout, tilesX);
    } else {
        if (Ci % 4 == 0)
            conv_pac_kernel<2, 4><<<grid, 256>>>(in, w, b, kern, out, Ci, Co, Hin, Win, Hout, Wout, tilesX);
        else
            conv_pac_kernel<2, 1><<<grid, 256>>>(in, w, b, kern, out, Ci, Co, Hin, Win, Hout, Wout, tilesX);
    }
}

static void pac_layer(const float* f, float* out, int C, int H, int W, float coeff2)
{
    int hw = H * W;
    dim3 grid((hw + 255) / 256, 1, 2);
    pac_gauss_kernel<<<grid, 256>>>(f, out, C, H, W, coeff2);
}

extern "C" void kernel_launch(void* const* d_in, const int* in_sizes, int n_in,
                              void* d_out, int out_size)
{
    const float* x = (const float*)d_in[0];
    const float* W[14];
    const float* B[14];
    for (int i = 0; i < 14; i++) {
        W[i] = (const float*)d_in[1 + 2 * i];
        B[i] = (const float*)d_in[2 + 2 * i];
    }

    float* bufA; float* bufB;
    cudaGetSymbolAddress((void**)&bufA, g_bufA);
    cudaGetSymbolAddress((void**)&bufB, g_bufB);

    float* out = (float*)d_out;
    float* h1 = out;                     // 2*64*256*256   = 8388608
    float* h2 = h1 + 8388608;            // 2*128*128*128  = 4194304
    float* h3 = h2 + 4194304;            // 2*256*64*64    = 2097152
    float* h4 = h3 + 2097152;            // 2*512*32*32    = 1048576
    float* h5 = h4 + 1048576;            // 2*1024*16*16   = 524288
    float* k2 = h5 + 524288;             // 2*9*128*128    = 294912
    float* k3 = k2 + 294912;             // 2*9*64*64      = 73728
    float* k4 = k3 + 73728;              // 2*9*32*32      = 18432
    float* k5 = k4 + 18432;              // 2*9*16*16      = 4608

    const float KC2 = 1e-4f * 1e-4f;

    // Stage 1
    conv_layer(x,    W[0], B[0], nullptr, bufA, 1,  64, 256, 256, 1);
    conv_layer(bufA, W[1], B[1], nullptr, h1,   64, 64, 256, 256, 1);
    conv_layer(h1,   W[2], B[2], nullptr, bufA, 64, 64, 256, 256, 2);  // -> 2,64,128,128

    // Stage 2 (PAC)
    pac_layer(bufA, k2, 64, 128, 128, KC2);
    conv_layer(bufA, W[3], B[3], k2, bufB, 64,  128, 128, 128, 1);
    conv_layer(bufB, W[4], B[4], k2, h2,   128, 128, 128, 128, 1);
    conv_layer(h2,   W[5], B[5], k2, bufA, 128, 128, 128, 128, 2);     // -> 2,128,64,64

    // Stage 3
    pac_layer(bufA, k3, 128, 64, 64, KC2);
    conv_layer(bufA, W[6], B[6], k3, bufB, 128, 256, 64, 64, 1);
    conv_layer(bufB, W[7], B[7], k3, h3,   256, 256, 64, 64, 1);
    conv_layer(h3,   W[8], B[8], k3, bufA, 256, 256, 64, 64, 2);       // -> 2,256,32,32

    // Stage 4 (guidance scaled by 2.0 -> coeff^2 = 4)
    pac_layer(bufA, k4, 256, 32, 32, 4.0f);
    conv_layer(bufA, W[9],  B[9],  k4, bufB, 256, 512, 32, 32, 1);
    conv_layer(bufB, W[10], B[10], k4, h4,   512, 512, 32, 32, 1);
    conv_layer(h4,   W[11], B[11], k4, bufA, 512, 512, 32, 32, 2);     // -> 2,512,16,16

    // Stage 5
    pac_layer(bufA, k5, 512, 16, 16, KC2);
    conv_layer(bufA, W[12], B[12], k5, bufB, 512,  1024, 16, 16, 1);
    conv_layer(bufB, W[13], B[13], k5, h5,   1024, 1024, 16, 16, 1);
}